// round 12
// baseline (speedup 1.0000x reference)
#include <cuda_runtime.h>
#include <cstdint>
#include <math.h>

#define B_   16
#define L_   128
#define H_   1024
#define V_   50257
#define LM1  127
#define VP   50264          // padded V (mult of 8)
#define NB2  393            // ceil(V/128) blocks for projection
#define CW   3142           // 16 chunks cover V
#define CWP  3152           // padded chunk (mult of 16 floats)

// ---------------- scratch (device globals; no allocation allowed) ----------
__device__ __align__(16) float  g_x0[B_ * H_];
__device__ __align__(16) float  g_h0[B_ * H_];
__device__ __align__(16) float  g_h1f[128 * 128];    // h1 in mma A-frag layout
__device__ __align__(16) float  g_logits[B_ * VP];   // logits + bias
__device__ __align__(16) float  g_bsum[400 * B_];    // per-block sum(exp)

// ---------------- K0a: x0 = relu(emb[tok]) ----------------------------------
__global__ void k0a_embed(const int* __restrict__ inp,
                          const float* __restrict__ emb) {
    int id = blockIdx.x * blockDim.x + threadIdx.x;   // 0..16383
    int b = id >> 10;
    int h = id & (H_ - 1);
    int tok = inp[b * L_];                            // input[b, 0]
    g_x0[id] = fmaxf(emb[(size_t)tok * H_ + h], 0.0f);
}

// ---------------- K0b: h0 = bridge (half the batches per launch) ------------
__global__ void k0b_bridge(const float* __restrict__ hidden,
                           const float* __restrict__ bw,
                           const float* __restrict__ bb, int b0) {
    int id = blockIdx.x * blockDim.x + threadIdx.x;   // 0..8191
    int b = b0 + (id >> 10);
    int h = id & (H_ - 1);
    float acc = 0.0f;
    const float* hp = hidden + (size_t)b * L_ * H_ + h;
#pragma unroll 8
    for (int l = 0; l < L_; l++)
        acc += hp[(size_t)l * H_] * __ldg(bw + l);
    g_h0[b * H_ + h] = acc + __ldg(bb);
}

// ---------------- K1: GRU cell -> h1 (stored as tf32 A-fragments) -----------
__global__ void k1_gates(const float* __restrict__ w_ih,
                         const float* __restrict__ w_hh,
                         const float* __restrict__ b_ih,
                         const float* __restrict__ b_hh) {
    __shared__ __align__(16) float sw[6 * H_];        // 24 KB: 6 weight rows
    int j = blockIdx.x;                               // output column 0..1023
    int tid = threadIdx.x;

    const float* rows[6];
    rows[0] = w_ih + (size_t)j * H_;
    rows[1] = w_ih + (size_t)(j + H_) * H_;
    rows[2] = w_ih + (size_t)(j + 2 * H_) * H_;
    rows[3] = w_hh + (size_t)j * H_;
    rows[4] = w_hh + (size_t)(j + H_) * H_;
    rows[5] = w_hh + (size_t)(j + 2 * H_) * H_;
#pragma unroll
    for (int r = 0; r < 6; r++) {
        float4* dst = (float4*)(sw + r * H_);
        const float4* src = (const float4*)rows[r];
#pragma unroll 2
        for (int i = tid; i < H_ / 4; i += 128)
            dst[i] = __ldg(src + i);
    }
    __syncthreads();

    int warp = tid >> 5, lane = tid & 31;
#define DOT4(acc, vv, ww) \
    acc += vv.x * ww.x + vv.y * ww.y + vv.z * ww.z + vv.w * ww.w
    for (int bb4 = 0; bb4 < 4; bb4++) {
        int b = warp * 4 + bb4;
        float a0 = 0, a1 = 0, a2 = 0, a3 = 0, a4 = 0, a5 = 0;
        const float* xp = g_x0 + b * H_;
        const float* hp = g_h0 + b * H_;
#pragma unroll
        for (int k = lane * 4; k < H_; k += 128) {
            float4 x = *(const float4*)(xp + k);
            float4 h = *(const float4*)(hp + k);
            float4 w0 = *(const float4*)(sw + k);
            float4 w1 = *(const float4*)(sw + H_ + k);
            float4 w2 = *(const float4*)(sw + 2 * H_ + k);
            float4 w3 = *(const float4*)(sw + 3 * H_ + k);
            float4 w4 = *(const float4*)(sw + 4 * H_ + k);
            float4 w5 = *(const float4*)(sw + 5 * H_ + k);
            DOT4(a0, x, w0); DOT4(a1, x, w1); DOT4(a2, x, w2);
            DOT4(a3, h, w3); DOT4(a4, h, w4); DOT4(a5, h, w5);
        }
#pragma unroll
        for (int off = 16; off; off >>= 1) {
            a0 += __shfl_xor_sync(0xffffffffu, a0, off);
            a1 += __shfl_xor_sync(0xffffffffu, a1, off);
            a2 += __shfl_xor_sync(0xffffffffu, a2, off);
            a3 += __shfl_xor_sync(0xffffffffu, a3, off);
            a4 += __shfl_xor_sync(0xffffffffu, a4, off);
            a5 += __shfl_xor_sync(0xffffffffu, a5, off);
        }
        if (lane == 0) {
            float ir = a0 + __ldg(b_ih + j);
            float iz = a1 + __ldg(b_ih + j + H_);
            float in_ = a2 + __ldg(b_ih + j + 2 * H_);
            float hr = a3 + __ldg(b_hh + j);
            float hz = a4 + __ldg(b_hh + j + H_);
            float hn = a5 + __ldg(b_hh + j + 2 * H_);
            float r = 1.0f / (1.0f + expf(-(ir + hr)));
            float z = 1.0f / (1.0f + expf(-(iz + hz)));
            float n = tanhf(in_ + r * hn);
            float h0v = g_h0[b * H_ + j];
            float h1 = (1.0f - z) * n + z * h0v;
            // store in m16n8k8 A-fragment layout, rounded to tf32
            unsigned int tv;
            asm("cvt.rna.tf32.f32 %0, %1;" : "=r"(tv) : "f"(h1));
            int s = j >> 3;                       // kstep
            int lf = ((b & 7) << 2) | (j & 3);    // lane
            int rr = (b >> 3) + (((j >> 2) & 1) << 1);  // reg
            g_h1f[s * 128 + lf * 4 + rr] = __uint_as_float(tv);
        }
    }
#undef DOT4
}

// ---------------- K2: logits = h1 @ proj_w^T + b via mma.tf32 ---------------
// ring-3 of 128x16 w tiles, depth-2 in flight (wait_group 1)
#define NST  64                       // 64 stages of 16 k
#define WPAD 20                       // 16 + 4 pad floats per row

__global__ void __launch_bounds__(128, 5)
k2_proj(const float* __restrict__ pw, const float* __restrict__ pb) {
    __shared__ __align__(16) float shw[3][128 * WPAD]; // 30 KB w ring
    __shared__ __align__(16) float sha[2048];          // 8 KB A frags (one kt)
    __shared__ float red[4][B_];

    int tid = threadIdx.x;
    int warp = tid >> 5, lane = tid & 31;
    unsigned int shw_s0 = (unsigned int)__cvta_generic_to_shared(&shw[0][0]);

    // async-stage one 128x16 w tile (stage s covers k in [s*16, s*16+16))
    auto stage_load = [&](int s) {
        int kbase = s * 16;
        unsigned int base = shw_s0 + (unsigned int)(s % 3) * (128 * WPAD * 4);
#pragma unroll
        for (int i2 = 0; i2 < 4; i2++) {
            int i = tid + 128 * i2;
            int r = i >> 2, c = i & 3;
            int vr = blockIdx.x * 128 + r;
            int vr2 = (vr < V_) ? vr : (V_ - 1);
            const float* src = pw + (size_t)vr2 * H_ + kbase + c * 4;
            int sz = (vr < V_) ? 16 : 0;
            unsigned int dst = base + (unsigned int)(r * WPAD + c * 4) * 4;
            asm volatile("cp.async.cg.shared.global [%0], [%1], 16, %2;"
                         :: "r"(dst), "l"(src), "r"(sz));
        }
    };

    float d[4][4];
#pragma unroll
    for (int nt = 0; nt < 4; nt++)
#pragma unroll
        for (int p = 0; p < 4; p++) d[nt][p] = 0.0f;

    stage_load(0);
    asm volatile("cp.async.commit_group;");
    stage_load(1);
    asm volatile("cp.async.commit_group;");

    int rbase = warp * 32 + (lane >> 2);
    int cbase = lane & 3;

    for (int s = 0; s < NST; s++) {
        float4 af0, af1, af2, af3;
        if ((s & 7) == 0) {                 // hoist A loads (L2) over the wait
            const float4* asrc = (const float4*)(g_h1f + (s >> 3) * 2048);
            af0 = asrc[tid];       af1 = asrc[tid + 128];
            af2 = asrc[tid + 256]; af3 = asrc[tid + 384];
        }
        if (s < NST - 1)
            asm volatile("cp.async.wait_group 1;" ::: "memory");
        else
            asm volatile("cp.async.wait_group 0;" ::: "memory");
        __syncthreads();                    // tile s ready, compute s-1 done
        if (s + 2 < NST) {                  // keep 2 loads in flight
            stage_load(s + 2);
            asm volatile("cp.async.commit_group;");
        }
        if ((s & 7) == 0) {                 // publish A frags for this kt
            float4* ad = (float4*)sha;
            ad[tid] = af0;       ad[tid + 128] = af1;
            ad[tid + 256] = af2; ad[tid + 384] = af3;
            __syncthreads();
        }

        const float* wb = shw[s % 3];
#pragma unroll
        for (int q = 0; q < 2; q++) {
            int sl = (s & 7) * 2 + q;       // k8-step within this kt
            float4 av = *(const float4*)(sha + sl * 128 + lane * 4);
            unsigned int a0 = __float_as_uint(av.x), a1 = __float_as_uint(av.y);
            unsigned int a2 = __float_as_uint(av.z), a3 = __float_as_uint(av.w);
#pragma unroll
            for (int nt = 0; nt < 4; nt++) {
                const float* wr = wb + (rbase + nt * 8) * WPAD + q * 8 + cbase;
                unsigned int b0 = __float_as_uint(wr[0]);
                unsigned int b1 = __float_as_uint(wr[4]);
                asm volatile(
                    "mma.sync.aligned.m16n8k8.row.col.f32.tf32.tf32.f32 "
                    "{%0,%1,%2,%3}, {%4,%5,%6,%7}, {%8,%9}, {%0,%1,%2,%3};"
                    : "+f"(d[nt][0]), "+f"(d[nt][1]),
                      "+f"(d[nt][2]), "+f"(d[nt][3])
                    : "r"(a0), "r"(a1), "r"(a2), "r"(a3), "r"(b0), "r"(b1));
            }
        }
    }

    // epilogue: bias, store logits, per-block sum(exp) partials
    float slo = 0.0f, shi = 0.0f;
    int vb = blockIdx.x * 128 + warp * 32;
    int blo = lane >> 2;
#pragma unroll
    for (int nt = 0; nt < 4; nt++) {
        int v0 = vb + nt * 8 + (lane & 3) * 2;
        int v1 = v0 + 1;
        float bi0 = __ldg(pb + (v0 < V_ ? v0 : V_ - 1));
        float bi1 = __ldg(pb + (v1 < V_ ? v1 : V_ - 1));
        float x0 = d[nt][0] + bi0, x1 = d[nt][1] + bi1;
        float x2 = d[nt][2] + bi0, x3 = d[nt][3] + bi1;
        if (v0 < V_) {
            g_logits[blo * VP + v0] = x0;
            g_logits[(blo + 8) * VP + v0] = x2;
            slo += __expf(x0); shi += __expf(x2);
        }
        if (v1 < V_) {
            g_logits[blo * VP + v1] = x1;
            g_logits[(blo + 8) * VP + v1] = x3;
            slo += __expf(x1); shi += __expf(x3);
        }
    }
    slo += __shfl_xor_sync(0xffffffffu, slo, 1);
    slo += __shfl_xor_sync(0xffffffffu, slo, 2);
    shi += __shfl_xor_sync(0xffffffffu, shi, 1);
    shi += __shfl_xor_sync(0xffffffffu, shi, 2);
    if ((lane & 3) == 0) {
        red[warp][blo] = slo;
        red[warp][blo + 8] = shi;
    }
    __syncthreads();
    if (tid < B_)
        g_bsum[blockIdx.x * B_ + tid] =
            red[0][tid] + red[1][tid] + red[2][tid] + red[3][tid];
}

// ---------------- K4: logZ prologue + TMA-bulk broadcast write ---------------
// grid = 16 b x 16 chunks x 4 t-quarters = 1024 blocks
__global__ void __launch_bounds__(256)
k4_bcast(float* __restrict__ out) {
    __shared__ __align__(16) float sh[CWP];
    __shared__ __align__(16) float shs[3][CWP];    // shifted by 1,2,3 floats
    __shared__ float wsum[8];
    __shared__ float slz;
    int tid = threadIdx.x;
    int b = blockIdx.x >> 6;
    int chunk = (blockIdx.x >> 2) & 15;
    int tq = blockIdx.x & 3;
    int c0 = chunk * CW;
    int cw = V_ - c0; if (cw > CW) cw = CW;
    int t0 = tq * 32;
    int t1 = t0 + 32; if (t1 > LM1) t1 = LM1;

    // deterministic logZ reduction over K2's per-block partials
    float s = 0.0f;
    for (int i = tid; i < NB2; i += 256) s += g_bsum[i * B_ + b];
#pragma unroll
    for (int off = 16; off; off >>= 1)
        s += __shfl_xor_sync(0xffffffffu, s, off);
    int lane = tid & 31, warp = tid >> 5;
    if (lane == 0) wsum[warp] = s;
    __syncthreads();
    if (tid == 0) {
        float t = 0.0f;
#pragma unroll
        for (int w = 0; w < 8; w++) t += wsum[w];
        slz = logf(t);
    }
    __syncthreads();
    float lz = slz;

    for (int i = tid; i < cw; i += 256)
        sh[i] = g_logits[b * VP + c0 + i] - lz;
    for (int i = cw + tid; i < CWP; i += 256)
        sh[i] = 0.0f;
    __syncthreads();
#pragma unroll
    for (int ss = 0; ss < 3; ss++)
        for (int i = tid; i + ss + 1 < CWP; i += 256)
            shs[ss][i] = sh[i + ss + 1];
    __syncthreads();
    asm volatile("fence.proxy.async.shared::cta;" ::: "memory");

    // rows round-robined over 8 warps; lane0 issues one bulk copy per row
    size_t base0 = (size_t)b * LM1 * V_ + c0;
    for (int t = t0 + warp; t < t1; t += 8) {
        size_t base = base0 + (size_t)t * V_;
        int a = (int)(base & 3);
        int head = (4 - a) & 3;
        int nf4 = (cw - head) >> 2;
        int done = head + 4 * nf4;
        int rem = cw - done;
        if (lane >= 1 && lane <= head)
            out[base + lane - 1] = sh[lane - 1];
        if (lane >= 4 && lane < 4 + rem)
            out[base + done + lane - 4] = sh[done + lane - 4];
        if (lane == 0) {
            const float* srcp = head ? shs[head - 1] : sh;
            unsigned int saddr = (unsigned int)__cvta_generic_to_shared(srcp);
            asm volatile(
                "cp.async.bulk.global.shared::cta.bulk_group [%0], [%1], %2;"
                :: "l"(out + base + head), "r"(saddr), "r"(nf4 * 16)
                : "memory");
        }
    }
    if (lane == 0) {
        asm volatile("cp.async.bulk.commit_group;" ::: "memory");
        asm volatile("cp.async.bulk.wait_group 0;" ::: "memory");
    }
}

// ---------------- launch -----------------------------------------------------
extern "C" void kernel_launch(void* const* d_in, const int* in_sizes, int n_in,
                              void* d_out, int out_size) {
    const int*   inp    = (const int*)d_in[0];
    const float* hidden = (const float*)d_in[1];
    const float* emb    = (const float*)d_in[2];
    const float* bw     = (const float*)d_in[3];
    const float* bb     = (const float*)d_in[4];
    const float* w_ih   = (const float*)d_in[5];
    const float* w_hh   = (const float*)d_in[6];
    const float* b_ih   = (const float*)d_in[7];
    const float* b_hh   = (const float*)d_in[8];
    const float* pw     = (const float*)d_in[9];
    const float* pb     = (const float*)d_in[10];
    float* out = (float*)d_out;

    k0a_embed<<<64, 256>>>(inp, emb);
    k0b_bridge<<<32, 256>>>(hidden, bw, bb, 0);
    k0b_bridge<<<32, 256>>>(hidden, bw, bb, 8);
    k1_gates<<<H_, 128>>>(w_ih, w_hh, b_ih, b_hh);   // <-- ncu slot 6
    k2_proj<<<NB2, 128>>>(pw, pb);
    k4_bcast<<<16 * 16 * 4, 256>>>(out);
}

// round 14
// speedup vs baseline: 1.0772x; 1.0772x over previous
#include <cuda_runtime.h>
#include <cstdint>
#include <math.h>

#define B_   16
#define L_   128
#define H_   1024
#define V_   50257
#define LM1  127
#define VP   50264          // padded V (mult of 8)
#define NB2  393            // ceil(V/128) blocks for projection
#define CW   3142           // 16 chunks cover V
#define CWP  3152           // padded chunk (mult of 16 floats)

// ---------------- scratch (device globals; no allocation allowed) ----------
__device__ __align__(16) float  g_h0[B_ * H_];       // plain h0 [b][j]
__device__ __align__(16) float  g_x0f[128 * 128];    // x0 in mma A-frag layout
__device__ __align__(16) float  g_h0f[128 * 128];    // h0 in mma A-frag layout
__device__ __align__(16) float  g_h1f[128 * 128];    // h1 in mma A-frag layout
__device__ __align__(16) float  g_gates[6144 * B_];  // raw gi/gh + bias [j'][b]
__device__ __align__(16) float  g_logits[B_ * VP];   // logits + bias
__device__ __align__(16) float  g_bsum[400 * B_];    // per-block sum(exp)

__device__ __forceinline__ void frag_store(float* dst, int b, int j, float v) {
    unsigned int tv;
    asm("cvt.rna.tf32.f32 %0, %1;" : "=r"(tv) : "f"(v));
    int s = j >> 3;
    int lf = ((b & 7) << 2) | (j & 3);
    int rr = (b >> 3) + (((j >> 2) & 1) << 1);
    dst[s * 128 + lf * 4 + rr] = __uint_as_float(tv);
}

// ---------------- K0: x0 = relu(emb[tok]), h0 = bridge; frag stores ---------
__global__ void k0_prep(const int* __restrict__ inp,
                        const float* __restrict__ hidden,
                        const float* __restrict__ emb,
                        const float* __restrict__ bw,
                        const float* __restrict__ bb) {
    int id = blockIdx.x * blockDim.x + threadIdx.x;   // 0..16383
    int b = id >> 10;
    int h = id & (H_ - 1);
    int tok = inp[b * L_];                            // input[b, 0]
    float x0 = fmaxf(emb[(size_t)tok * H_ + h], 0.0f);
    float acc = 0.0f;
    const float* hp = hidden + (size_t)b * L_ * H_ + h;
#pragma unroll 8
    for (int l = 0; l < L_; l++)
        acc += hp[(size_t)l * H_] * __ldg(bw + l);
    float h0 = acc + __ldg(bb);
    g_h0[id] = h0;
    frag_store(g_x0f, b, h, x0);
    frag_store(g_h0f, b, h, h0);
}

// ---------------- K1a: gates GEMM via mma.tf32 ------------------------------
// rows 0..3071: gi = x0 @ w_ih^T + b_ih ; rows 3072..6143: gh = h0 @ w_hh^T + b_hh
// grid = 96 blocks x 64 rows, double-buffered 64x32 w tiles
__global__ void __launch_bounds__(128, 4)
k1a_gemm(const float* __restrict__ w_ih, const float* __restrict__ w_hh,
         const float* __restrict__ b_ih, const float* __restrict__ b_hh) {
    __shared__ __align__(16) float shw[2][64 * 36];  // 18.4 KB w ring
    __shared__ __align__(16) float sha[2048];        // 8 KB A frags (one kt)

    int tid = threadIdx.x;
    int warp = tid >> 5, lane = tid & 31;
    int bi = blockIdx.x;
    int grp = (bi >= 48);
    const float* wsel = grp ? w_hh : w_ih;
    const float* bsel = grp ? b_hh : b_ih;
    const float* af   = grp ? g_h0f : g_x0f;
    int rowm0 = bi * 64 - grp * 3072;                // row base within matrix
    unsigned int shw_s0 = (unsigned int)__cvta_generic_to_shared(&shw[0][0]);

    auto stage_load = [&](int s) {                   // 64 rows x 32 k
        int kbase = s * 32;
        unsigned int base = shw_s0 + (unsigned int)(s & 1) * (64 * 36 * 4);
#pragma unroll
        for (int i2 = 0; i2 < 4; i2++) {
            int i = tid + 128 * i2;
            int r = i >> 3, c = i & 7;
            const float* src = wsel + (size_t)(rowm0 + r) * H_ + kbase + c * 4;
            unsigned int dst = base + (unsigned int)(r * 36 + c * 4) * 4;
            asm volatile("cp.async.cg.shared.global [%0], [%1], 16, 16;"
                         :: "r"(dst), "l"(src));
        }
    };

    float d[2][4];
#pragma unroll
    for (int nt = 0; nt < 2; nt++)
#pragma unroll
        for (int p = 0; p < 4; p++) d[nt][p] = 0.0f;

    stage_load(0);
    asm volatile("cp.async.commit_group;");

    int rbase = warp * 16 + (lane >> 2);
    int cbase = lane & 3;

    for (int s = 0; s < 32; s++) {
        float4 af0, af1, af2, af3;
        if ((s & 3) == 0) {
            const float4* asrc = (const float4*)(af + (s >> 2) * 2048);
            af0 = asrc[tid];       af1 = asrc[tid + 128];
            af2 = asrc[tid + 256]; af3 = asrc[tid + 384];
        }
        asm volatile("cp.async.wait_group 0;" ::: "memory");
        __syncthreads();
        if (s + 1 < 32) {
            stage_load(s + 1);
            asm volatile("cp.async.commit_group;");
        }
        if ((s & 3) == 0) {
            float4* ad = (float4*)sha;
            ad[tid] = af0;       ad[tid + 128] = af1;
            ad[tid + 256] = af2; ad[tid + 384] = af3;
            __syncthreads();
        }

        const float* wb = shw[s & 1];
#pragma unroll
        for (int q = 0; q < 4; q++) {
            int sl = (s & 3) * 4 + q;
            float4 av = *(const float4*)(sha + sl * 128 + lane * 4);
            unsigned int a0 = __float_as_uint(av.x), a1 = __float_as_uint(av.y);
            unsigned int a2 = __float_as_uint(av.z), a3 = __float_as_uint(av.w);
#pragma unroll
            for (int nt = 0; nt < 2; nt++) {
                const float* wr = wb + (rbase + nt * 8) * 36 + q * 8 + cbase;
                unsigned int b0 = __float_as_uint(wr[0]);
                unsigned int b1 = __float_as_uint(wr[4]);
                asm volatile(
                    "mma.sync.aligned.m16n8k8.row.col.f32.tf32.tf32.f32 "
                    "{%0,%1,%2,%3}, {%4,%5,%6,%7}, {%8,%9}, {%0,%1,%2,%3};"
                    : "+f"(d[nt][0]), "+f"(d[nt][1]),
                      "+f"(d[nt][2]), "+f"(d[nt][3])
                    : "r"(a0), "r"(a1), "r"(a2), "r"(a3), "r"(b0), "r"(b1));
            }
        }
    }

    // epilogue: add bias, write raw gates G[j'][b]
    int blo = lane >> 2;
#pragma unroll
    for (int nt = 0; nt < 2; nt++) {
        int jg = bi * 64 + warp * 16 + nt * 8 + (lane & 3) * 2;  // global row
        int jl = jg - grp * 3072;
        float bi0 = __ldg(bsel + jl);
        float bi1 = __ldg(bsel + jl + 1);
        g_gates[jg * B_ + blo]           = d[nt][0] + bi0;
        g_gates[jg * B_ + blo + 8]       = d[nt][2] + bi0;
        g_gates[(jg + 1) * B_ + blo]     = d[nt][1] + bi1;
        g_gates[(jg + 1) * B_ + blo + 8] = d[nt][3] + bi1;
    }
}

// ---------------- K1b: GRU nonlinearity -> h1 frags -------------------------
__global__ void k1b_nonlin() {
    int id = blockIdx.x * blockDim.x + threadIdx.x;   // 0..16383
    int j = id >> 4, b = id & 15;
    float ir  = g_gates[j * B_ + b];
    float iz  = g_gates[(j + 1024) * B_ + b];
    float in_ = g_gates[(j + 2048) * B_ + b];
    float hr  = g_gates[(j + 3072) * B_ + b];
    float hz  = g_gates[(j + 4096) * B_ + b];
    float hn  = g_gates[(j + 5120) * B_ + b];
    float r = 1.0f / (1.0f + expf(-(ir + hr)));
    float z = 1.0f / (1.0f + expf(-(iz + hz)));
    float n = tanhf(in_ + r * hn);
    float h0v = g_h0[b * H_ + j];
    float h1 = (1.0f - z) * n + z * h0v;
    frag_store(g_h1f, b, j, h1);
}

// ---------------- K2: logits = h1 @ proj_w^T + b via mma.tf32 (R11 ver) -----
__global__ void __launch_bounds__(128, 4)
k2_proj(const float* __restrict__ pw, const float* __restrict__ pb) {
    __shared__ __align__(16) float shw[2][128 * 36]; // 36.9 KB w ring
    __shared__ __align__(16) float sha[2048];        // 8 KB A frags (one kt)
    __shared__ float red[4][B_];

    int tid = threadIdx.x;
    int warp = tid >> 5, lane = tid & 31;
    unsigned int shw_s0 = (unsigned int)__cvta_generic_to_shared(&shw[0][0]);

    auto stage_load = [&](int s) {
        int kbase = s * 32;
        unsigned int base = shw_s0 + (unsigned int)(s & 1) * (128 * 36 * 4);
#pragma unroll
        for (int i2 = 0; i2 < 8; i2++) {
            int i = tid + 128 * i2;
            int r = i >> 3, c = i & 7;
            int vr = blockIdx.x * 128 + r;
            int vr2 = (vr < V_) ? vr : (V_ - 1);
            const float* src = pw + (size_t)vr2 * H_ + kbase + c * 4;
            int sz = (vr < V_) ? 16 : 0;
            unsigned int dst = base + (unsigned int)(r * 36 + c * 4) * 4;
            asm volatile("cp.async.cg.shared.global [%0], [%1], 16, %2;"
                         :: "r"(dst), "l"(src), "r"(sz));
        }
    };

    float d[4][4];
#pragma unroll
    for (int nt = 0; nt < 4; nt++)
#pragma unroll
        for (int p = 0; p < 4; p++) d[nt][p] = 0.0f;

    stage_load(0);
    asm volatile("cp.async.commit_group;");

    int rbase = warp * 32 + (lane >> 2);
    int cbase = lane & 3;

    for (int s = 0; s < 32; s++) {
        float4 af0, af1, af2, af3;
        if ((s & 3) == 0) {                 // hoist A loads (L2) over the wait
            const float4* asrc = (const float4*)(g_h1f + (s >> 2) * 2048);
            af0 = asrc[tid];       af1 = asrc[tid + 128];
            af2 = asrc[tid + 256]; af3 = asrc[tid + 384];
        }
        asm volatile("cp.async.wait_group 0;" ::: "memory");
        __syncthreads();                    // tile s ready, prev compute done
        if (s + 1 < 32) {
            stage_load(s + 1);
            asm volatile("cp.async.commit_group;");
        }
        if ((s & 3) == 0) {                 // publish A frags for this kt
            float4* ad = (float4*)sha;
            ad[tid] = af0;       ad[tid + 128] = af1;
            ad[tid + 256] = af2; ad[tid + 384] = af3;
            __syncthreads();
        }

        const float* wb = shw[s & 1];
#pragma unroll
        for (int q = 0; q < 4; q++) {
            int sl = (s & 3) * 4 + q;
            float4 av = *(const float4*)(sha + sl * 128 + lane * 4);
            unsigned int a0 = __float_as_uint(av.x), a1 = __float_as_uint(av.y);
            unsigned int a2 = __float_as_uint(av.z), a3 = __float_as_uint(av.w);
#pragma unroll
            for (int nt = 0; nt < 4; nt++) {
                const float* wr = wb + (rbase + nt * 8) * 36 + q * 8 + cbase;
                unsigned int b0 = __float_as_uint(wr[0]);
                unsigned int b1 = __float_as_uint(wr[4]);
                asm volatile(
                    "mma.sync.aligned.m16n8k8.row.col.f32.tf32.tf32.f32 "
                    "{%0,%1,%2,%3}, {%4,%5,%6,%7}, {%8,%9}, {%0,%1,%2,%3};"
                    : "+f"(d[nt][0]), "+f"(d[nt][1]),
                      "+f"(d[nt][2]), "+f"(d[nt][3])
                    : "r"(a0), "r"(a1), "r"(a2), "r"(a3), "r"(b0), "r"(b1));
            }
        }
    }

    // epilogue: bias, store logits, per-block sum(exp) partials
    float slo = 0.0f, shi = 0.0f;
    int vb = blockIdx.x * 128 + warp * 32;
    int blo = lane >> 2;
#pragma unroll
    for (int nt = 0; nt < 4; nt++) {
        int v0 = vb + nt * 8 + (lane & 3) * 2;
        int v1 = v0 + 1;
        float bi0 = __ldg(pb + (v0 < V_ ? v0 : V_ - 1));
        float bi1 = __ldg(pb + (v1 < V_ ? v1 : V_ - 1));
        float x0 = d[nt][0] + bi0, x1 = d[nt][1] + bi1;
        float x2 = d[nt][2] + bi0, x3 = d[nt][3] + bi1;
        if (v0 < V_) {
            g_logits[blo * VP + v0] = x0;
            g_logits[(blo + 8) * VP + v0] = x2;
            slo += __expf(x0); shi += __expf(x2);
        }
        if (v1 < V_) {
            g_logits[blo * VP + v1] = x1;
            g_logits[(blo + 8) * VP + v1] = x3;
            slo += __expf(x1); shi += __expf(x3);
        }
    }
    slo += __shfl_xor_sync(0xffffffffu, slo, 1);
    slo += __shfl_xor_sync(0xffffffffu, slo, 2);
    shi += __shfl_xor_sync(0xffffffffu, shi, 1);
    shi += __shfl_xor_sync(0xffffffffu, shi, 2);
    if ((lane & 3) == 0) {
        red[warp][blo] = slo;
        red[warp][blo + 8] = shi;
    }
    __syncthreads();
    if (tid < B_)
        g_bsum[blockIdx.x * B_ + tid] =
            red[0][tid] + red[1][tid] + red[2][tid] + red[3][tid];
}

// ---------------- K4: logZ prologue + TMA-bulk broadcast write ---------------
// grid = 16 b x 16 chunks x 4 t-quarters = 1024 blocks
__global__ void __launch_bounds__(256)
k4_bcast(float* __restrict__ out) {
    __shared__ __align__(16) float sh[CWP];
    __shared__ __align__(16) float shs[3][CWP];    // shifted by 1,2,3 floats
    __shared__ float wsum[8];
    __shared__ float slz;
    int tid = threadIdx.x;
    int b = blockIdx.x >> 6;
    int chunk = (blockIdx.x >> 2) & 15;
    int tq = blockIdx.x & 3;
    int c0 = chunk * CW;
    int cw = V_ - c0; if (cw > CW) cw = CW;
    int t0 = tq * 32;
    int t1 = t0 + 32; if (t1 > LM1) t1 = LM1;

    // deterministic logZ reduction over K2's per-block partials
    float s = 0.0f;
    for (int i = tid; i < NB2; i += 256) s += g_bsum[i * B_ + b];
#pragma unroll
    for (int off = 16; off; off >>= 1)
        s += __shfl_xor_sync(0xffffffffu, s, off);
    int lane = tid & 31, warp = tid >> 5;
    if (lane == 0) wsum[warp] = s;
    __syncthreads();
    if (tid == 0) {
        float t = 0.0f;
#pragma unroll
        for (int w = 0; w < 8; w++) t += wsum[w];
        slz = logf(t);
    }
    __syncthreads();
    float lz = slz;

    for (int i = tid; i < cw; i += 256)
        sh[i] = g_logits[b * VP + c0 + i] - lz;
    for (int i = cw + tid; i < CWP; i += 256)
        sh[i] = 0.0f;
    __syncthreads();
#pragma unroll
    for (int ss = 0; ss < 3; ss++)
        for (int i = tid; i + ss + 1 < CWP; i += 256)
            shs[ss][i] = sh[i + ss + 1];
    __syncthreads();
    asm volatile("fence.proxy.async.shared::cta;" ::: "memory");

    // rows round-robined over 8 warps; lane0 issues one bulk copy per row
    size_t base0 = (size_t)b * LM1 * V_ + c0;
    for (int t = t0 + warp; t < t1; t += 8) {
        size_t base = base0 + (size_t)t * V_;
        int a = (int)(base & 3);
        int head = (4 - a) & 3;
        int nf4 = (cw - head) >> 2;
        int done = head + 4 * nf4;
        int rem = cw - done;
        if (lane >= 1 && lane <= head)
            out[base + lane - 1] = sh[lane - 1];
        if (lane >= 4 && lane < 4 + rem)
            out[base + done + lane - 4] = sh[done + lane - 4];
        if (lane == 0) {
            const float* srcp = head ? shs[head - 1] : sh;
            unsigned int saddr = (unsigned int)__cvta_generic_to_shared(srcp);
            asm volatile(
                "cp.async.bulk.global.shared::cta.bulk_group [%0], [%1], %2;"
                :: "l"(out + base + head), "r"(saddr), "r"(nf4 * 16)
                : "memory");
        }
    }
    if (lane == 0) {
        asm volatile("cp.async.bulk.commit_group;" ::: "memory");
        asm volatile("cp.async.bulk.wait_group 0;" ::: "memory");
    }
}

// ---------------- launch -----------------------------------------------------
extern "C" void kernel_launch(void* const* d_in, const int* in_sizes, int n_in,
                              void* d_out, int out_size) {
    const int*   inp    = (const int*)d_in[0];
    const float* hidden = (const float*)d_in[1];
    const float* emb    = (const float*)d_in[2];
    const float* bw     = (const float*)d_in[3];
    const float* bb     = (const float*)d_in[4];
    const float* w_ih   = (const float*)d_in[5];
    const float* w_hh   = (const float*)d_in[6];
    const float* b_ih   = (const float*)d_in[7];
    const float* b_hh   = (const float*)d_in[8];
    const float* pw     = (const float*)d_in[9];
    const float* pb     = (const float*)d_in[10];
    float* out = (float*)d_out;

    k0_prep<<<64, 256>>>(inp, hidden, emb, bw, bb);
    k1a_gemm<<<96, 128>>>(w_ih, w_hh, b_ih, b_hh);
    k1b_nonlin<<<64, 256>>>();
    k2_proj<<<NB2, 128>>>(pw, pb);          // <-- ncu slot 6 (4th launch)
    k4_bcast<<<16 * 16 * 4, 256>>>(out);
}

// round 15
// speedup vs baseline: 1.1878x; 1.1027x over previous
#include <cuda_runtime.h>
#include <cstdint>
#include <math.h>

#define B_   16
#define L_   128
#define H_   1024
#define V_   50257
#define LM1  127
#define VP   50264          // padded V (mult of 8)
#define NB2  393            // ceil(V/128) blocks for projection
#define CW   3142           // 16 chunks cover V
#define CWP  3152           // padded chunk (mult of 16 floats)

// k2 dynamic smem layout (floats): 3 w-buffers + A frags + reduction
#define K2_WBUF (128 * 36)
#define K2_SHA  (3 * K2_WBUF)
#define K2_RED  (K2_SHA + 2048)
#define K2_SMEM ((K2_RED + 64) * 4)     // bytes = 63.7 KB

// ---------------- scratch (device globals; no allocation allowed) ----------
__device__ __align__(16) float  g_h0[B_ * H_];       // plain h0 [b][j]
__device__ __align__(16) float  g_x0f[128 * 128];    // x0 in mma A-frag layout
__device__ __align__(16) float  g_h0f[128 * 128];    // h0 in mma A-frag layout
__device__ __align__(16) float  g_h1f[128 * 128];    // h1 in mma A-frag layout
__device__ __align__(16) float  g_gates[6144 * B_];  // raw gi/gh + bias [j'][b]
__device__ __align__(16) float  g_logits[B_ * VP];   // logits + bias
__device__ __align__(16) float  g_bsum[400 * B_];    // per-block sum(exp)

__device__ __forceinline__ void frag_store(float* dst, int b, int j, float v) {
    unsigned int tv;
    asm("cvt.rna.tf32.f32 %0, %1;" : "=r"(tv) : "f"(v));
    int s = j >> 3;
    int lf = ((b & 7) << 2) | (j & 3);
    int rr = (b >> 3) + (((j >> 2) & 1) << 1);
    dst[s * 128 + lf * 4 + rr] = __uint_as_float(tv);
}

// ---------------- K0: x0 = relu(emb[tok]), h0 = bridge; frag stores ---------
__global__ void k0_prep(const int* __restrict__ inp,
                        const float* __restrict__ hidden,
                        const float* __restrict__ emb,
                        const float* __restrict__ bw,
                        const float* __restrict__ bb) {
    int id = blockIdx.x * blockDim.x + threadIdx.x;   // 0..16383
    int b = id >> 10;
    int h = id & (H_ - 1);
    int tok = inp[b * L_];                            // input[b, 0]
    float x0 = fmaxf(emb[(size_t)tok * H_ + h], 0.0f);
    float acc = 0.0f;
    const float* hp = hidden + (size_t)b * L_ * H_ + h;
#pragma unroll 8
    for (int l = 0; l < L_; l++)
        acc += hp[(size_t)l * H_] * __ldg(bw + l);
    float h0 = acc + __ldg(bb);
    g_h0[id] = h0;
    frag_store(g_x0f, b, h, x0);
    frag_store(g_h0f, b, h, h0);
}

// ---------------- K1a: gates GEMM via mma.tf32, ring-4 pipeline -------------
__global__ void __launch_bounds__(128, 4)
k1a_gemm(const float* __restrict__ w_ih, const float* __restrict__ w_hh,
         const float* __restrict__ b_ih, const float* __restrict__ b_hh) {
    __shared__ __align__(16) float shw[4][64 * 36];  // 36.9 KB w ring
    __shared__ __align__(16) float sha[2048];        // 8 KB A frags (one kt)

    int tid = threadIdx.x;
    int warp = tid >> 5, lane = tid & 31;
    int bi = blockIdx.x;
    int grp = (bi >= 48);
    const float* wsel = grp ? w_hh : w_ih;
    const float* bsel = grp ? b_hh : b_ih;
    const float* af   = grp ? g_h0f : g_x0f;
    int rowm0 = bi * 64 - grp * 3072;                // row base within matrix
    unsigned int shw_s0 = (unsigned int)__cvta_generic_to_shared(&shw[0][0]);

    auto stage_load = [&](int s) {                   // 64 rows x 32 k
        int kbase = s * 32;
        unsigned int base = shw_s0 + (unsigned int)(s & 3) * (64 * 36 * 4);
#pragma unroll
        for (int i2 = 0; i2 < 4; i2++) {
            int i = tid + 128 * i2;
            int r = i >> 3, c = i & 7;
            const float* src = wsel + (size_t)(rowm0 + r) * H_ + kbase + c * 4;
            unsigned int dst = base + (unsigned int)(r * 36 + c * 4) * 4;
            asm volatile("cp.async.cg.shared.global [%0], [%1], 16, 16;"
                         :: "r"(dst), "l"(src));
        }
    };

    float d[2][4];
#pragma unroll
    for (int nt = 0; nt < 2; nt++)
#pragma unroll
        for (int p = 0; p < 4; p++) d[nt][p] = 0.0f;

    stage_load(0);
    asm volatile("cp.async.commit_group;");
    stage_load(1);
    asm volatile("cp.async.commit_group;");
    stage_load(2);
    asm volatile("cp.async.commit_group;");

    int rbase = warp * 16 + (lane >> 2);
    int cbase = lane & 3;

    for (int s = 0; s < 32; s++) {
        float4 af0, af1, af2, af3;
        if ((s & 3) == 0) {
            const float4* asrc = (const float4*)(af + (s >> 2) * 2048);
            af0 = asrc[tid];       af1 = asrc[tid + 128];
            af2 = asrc[tid + 256]; af3 = asrc[tid + 384];
        }
        if (s < 30)
            asm volatile("cp.async.wait_group 2;" ::: "memory");
        else if (s == 30)
            asm volatile("cp.async.wait_group 1;" ::: "memory");
        else
            asm volatile("cp.async.wait_group 0;" ::: "memory");
        __syncthreads();
        if (s + 3 < 32) {
            stage_load(s + 3);
            asm volatile("cp.async.commit_group;");
        }
        if ((s & 3) == 0) {
            float4* ad = (float4*)sha;
            ad[tid] = af0;       ad[tid + 128] = af1;
            ad[tid + 256] = af2; ad[tid + 384] = af3;
            __syncthreads();
        }

        const float* wb = shw[s & 3];
#pragma unroll
        for (int q = 0; q < 4; q++) {
            int sl = (s & 3) * 4 + q;
            float4 av = *(const float4*)(sha + sl * 128 + lane * 4);
            unsigned int a0 = __float_as_uint(av.x), a1 = __float_as_uint(av.y);
            unsigned int a2 = __float_as_uint(av.z), a3 = __float_as_uint(av.w);
#pragma unroll
            for (int nt = 0; nt < 2; nt++) {
                const float* wr = wb + (rbase + nt * 8) * 36 + q * 8 + cbase;
                unsigned int b0 = __float_as_uint(wr[0]);
                unsigned int b1 = __float_as_uint(wr[4]);
                asm volatile(
                    "mma.sync.aligned.m16n8k8.row.col.f32.tf32.tf32.f32 "
                    "{%0,%1,%2,%3}, {%4,%5,%6,%7}, {%8,%9}, {%0,%1,%2,%3};"
                    : "+f"(d[nt][0]), "+f"(d[nt][1]),
                      "+f"(d[nt][2]), "+f"(d[nt][3])
                    : "r"(a0), "r"(a1), "r"(a2), "r"(a3), "r"(b0), "r"(b1));
            }
        }
    }

    // epilogue: add bias, write raw gates G[j'][b]
    int blo = lane >> 2;
#pragma unroll
    for (int nt = 0; nt < 2; nt++) {
        int jg = bi * 64 + warp * 16 + nt * 8 + (lane & 3) * 2;  // global row
        int jl = jg - grp * 3072;
        float bi0 = __ldg(bsel + jl);
        float bi1 = __ldg(bsel + jl + 1);
        g_gates[jg * B_ + blo]           = d[nt][0] + bi0;
        g_gates[jg * B_ + blo + 8]       = d[nt][2] + bi0;
        g_gates[(jg + 1) * B_ + blo]     = d[nt][1] + bi1;
        g_gates[(jg + 1) * B_ + blo + 8] = d[nt][3] + bi1;
    }
}

// ---------------- K1b: GRU nonlinearity -> h1 frags -------------------------
__global__ void k1b_nonlin() {
    int id = blockIdx.x * blockDim.x + threadIdx.x;   // 0..16383
    int j = id >> 4, b = id & 15;
    float ir  = g_gates[j * B_ + b];
    float iz  = g_gates[(j + 1024) * B_ + b];
    float in_ = g_gates[(j + 2048) * B_ + b];
    float hr  = g_gates[(j + 3072) * B_ + b];
    float hz  = g_gates[(j + 4096) * B_ + b];
    float hn  = g_gates[(j + 5120) * B_ + b];
    float r = 1.0f / (1.0f + expf(-(ir + hr)));
    float z = 1.0f / (1.0f + expf(-(iz + hz)));
    float n = tanhf(in_ + r * hn);
    float h0v = g_h0[b * H_ + j];
    float h1 = (1.0f - z) * n + z * h0v;
    frag_store(g_h1f, b, j, h1);
}

// ---------------- K2: logits GEMM via mma.tf32, ring-3 (dynamic smem) -------
__global__ void __launch_bounds__(128)
k2_proj(const float* __restrict__ pw, const float* __restrict__ pb) {
    extern __shared__ __align__(16) float dyn[];
    float* sha = dyn + K2_SHA;
    float* red = dyn + K2_RED;

    int tid = threadIdx.x;
    int warp = tid >> 5, lane = tid & 31;
    unsigned int shw_s0 = (unsigned int)__cvta_generic_to_shared(dyn);

    auto stage_load = [&](int s) {
        int kbase = s * 32;
        unsigned int base = shw_s0 + (unsigned int)(s % 3) * (K2_WBUF * 4);
#pragma unroll
        for (int i2 = 0; i2 < 8; i2++) {
            int i = tid + 128 * i2;
            int r = i >> 3, c = i & 7;
            int vr = blockIdx.x * 128 + r;
            int vr2 = (vr < V_) ? vr : (V_ - 1);
            const float* src = pw + (size_t)vr2 * H_ + kbase + c * 4;
            int sz = (vr < V_) ? 16 : 0;
            unsigned int dst = base + (unsigned int)(r * 36 + c * 4) * 4;
            asm volatile("cp.async.cg.shared.global [%0], [%1], 16, %2;"
                         :: "r"(dst), "l"(src), "r"(sz));
        }
    };

    float d[4][4];
#pragma unroll
    for (int nt = 0; nt < 4; nt++)
#pragma unroll
        for (int p = 0; p < 4; p++) d[nt][p] = 0.0f;

    stage_load(0);
    asm volatile("cp.async.commit_group;");
    stage_load(1);
    asm volatile("cp.async.commit_group;");

    int rbase = warp * 32 + (lane >> 2);
    int cbase = lane & 3;

    for (int s = 0; s < 32; s++) {
        float4 af0, af1, af2, af3;
        if ((s & 3) == 0) {                 // hoist A loads (L2) over the wait
            const float4* asrc = (const float4*)(g_h1f + (s >> 2) * 2048);
            af0 = asrc[tid];       af1 = asrc[tid + 128];
            af2 = asrc[tid + 256]; af3 = asrc[tid + 384];
        }
        if (s < 31)
            asm volatile("cp.async.wait_group 1;" ::: "memory");
        else
            asm volatile("cp.async.wait_group 0;" ::: "memory");
        __syncthreads();                    // tile s ready, compute s-1 done
        if (s + 2 < 32) {                   // keep 2 stages in flight
            stage_load(s + 2);
            asm volatile("cp.async.commit_group;");
        }
        if ((s & 3) == 0) {                 // publish A frags for this kt
            float4* ad = (float4*)sha;
            ad[tid] = af0;       ad[tid + 128] = af1;
            ad[tid + 256] = af2; ad[tid + 384] = af3;
            __syncthreads();
        }

        const float* wb = dyn + (s % 3) * K2_WBUF;
#pragma unroll
        for (int q = 0; q < 4; q++) {
            int sl = (s & 3) * 4 + q;
            float4 av = *(const float4*)(sha + sl * 128 + lane * 4);
            unsigned int a0 = __float_as_uint(av.x), a1 = __float_as_uint(av.y);
            unsigned int a2 = __float_as_uint(av.z), a3 = __float_as_uint(av.w);
#pragma unroll
            for (int nt = 0; nt < 4; nt++) {
                const float* wr = wb + (rbase + nt * 8) * 36 + q * 8 + cbase;
                unsigned int b0 = __float_as_uint(wr[0]);
                unsigned int b1 = __float_as_uint(wr[4]);
                asm volatile(
                    "mma.sync.aligned.m16n8k8.row.col.f32.tf32.tf32.f32 "
                    "{%0,%1,%2,%3}, {%4,%5,%6,%7}, {%8,%9}, {%0,%1,%2,%3};"
                    : "+f"(d[nt][0]), "+f"(d[nt][1]),
                      "+f"(d[nt][2]), "+f"(d[nt][3])
                    : "r"(a0), "r"(a1), "r"(a2), "r"(a3), "r"(b0), "r"(b1));
            }
        }
    }

    // epilogue: bias, store logits, per-block sum(exp) partials
    float slo = 0.0f, shi = 0.0f;
    int vb = blockIdx.x * 128 + warp * 32;
    int blo = lane >> 2;
#pragma unroll
    for (int nt = 0; nt < 4; nt++) {
        int v0 = vb + nt * 8 + (lane & 3) * 2;
        int v1 = v0 + 1;
        float bi0 = __ldg(pb + (v0 < V_ ? v0 : V_ - 1));
        float bi1 = __ldg(pb + (v1 < V_ ? v1 : V_ - 1));
        float x0 = d[nt][0] + bi0, x1 = d[nt][1] + bi1;
        float x2 = d[nt][2] + bi0, x3 = d[nt][3] + bi1;
        if (v0 < V_) {
            g_logits[blo * VP + v0] = x0;
            g_logits[(blo + 8) * VP + v0] = x2;
            slo += __expf(x0); shi += __expf(x2);
        }
        if (v1 < V_) {
            g_logits[blo * VP + v1] = x1;
            g_logits[(blo + 8) * VP + v1] = x3;
            slo += __expf(x1); shi += __expf(x3);
        }
    }
    slo += __shfl_xor_sync(0xffffffffu, slo, 1);
    slo += __shfl_xor_sync(0xffffffffu, slo, 2);
    shi += __shfl_xor_sync(0xffffffffu, shi, 1);
    shi += __shfl_xor_sync(0xffffffffu, shi, 2);
    if ((lane & 3) == 0) {
        red[warp * B_ + blo] = slo;
        red[warp * B_ + blo + 8] = shi;
    }
    __syncthreads();
    if (tid < B_)
        g_bsum[blockIdx.x * B_ + tid] =
            red[tid] + red[B_ + tid] + red[2 * B_ + tid] + red[3 * B_ + tid];
}

// ---------------- K4: logZ prologue + TMA-bulk broadcast write ---------------
// grid = 16 b x 16 chunks x 4 t-quarters = 1024 blocks
__global__ void __launch_bounds__(256)
k4_bcast(float* __restrict__ out) {
    __shared__ __align__(16) float sh[CWP];
    __shared__ __align__(16) float shs[3][CWP];    // shifted by 1,2,3 floats
    __shared__ float wsum[8];
    __shared__ float slz;
    int tid = threadIdx.x;
    int b = blockIdx.x >> 6;
    int chunk = (blockIdx.x >> 2) & 15;
    int tq = blockIdx.x & 3;
    int c0 = chunk * CW;
    int cw = V_ - c0; if (cw > CW) cw = CW;
    int t0 = tq * 32;
    int t1 = t0 + 32; if (t1 > LM1) t1 = LM1;

    // deterministic logZ reduction over K2's per-block partials
    float s = 0.0f;
    for (int i = tid; i < NB2; i += 256) s += g_bsum[i * B_ + b];
#pragma unroll
    for (int off = 16; off; off >>= 1)
        s += __shfl_xor_sync(0xffffffffu, s, off);
    int lane = tid & 31, warp = tid >> 5;
    if (lane == 0) wsum[warp] = s;
    __syncthreads();
    if (tid == 0) {
        float t = 0.0f;
#pragma unroll
        for (int w = 0; w < 8; w++) t += wsum[w];
        slz = logf(t);
    }
    __syncthreads();
    float lz = slz;

    for (int i = tid; i < cw; i += 256)
        sh[i] = g_logits[b * VP + c0 + i] - lz;
    for (int i = cw + tid; i < CWP; i += 256)
        sh[i] = 0.0f;
    __syncthreads();
#pragma unroll
    for (int ss = 0; ss < 3; ss++)
        for (int i = tid; i + ss + 1 < CWP; i += 256)
            shs[ss][i] = sh[i + ss + 1];
    __syncthreads();
    asm volatile("fence.proxy.async.shared::cta;" ::: "memory");

    // rows round-robined over 8 warps; lane0 issues one bulk copy per row
    size_t base0 = (size_t)b * LM1 * V_ + c0;
    for (int t = t0 + warp; t < t1; t += 8) {
        size_t base = base0 + (size_t)t * V_;
        int a = (int)(base & 3);
        int head = (4 - a) & 3;
        int nf4 = (cw - head) >> 2;
        int done = head + 4 * nf4;
        int rem = cw - done;
        if (lane >= 1 && lane <= head)
            out[base + lane - 1] = sh[lane - 1];
        if (lane >= 4 && lane < 4 + rem)
            out[base + done + lane - 4] = sh[done + lane - 4];
        if (lane == 0) {
            const float* srcp = head ? shs[head - 1] : sh;
            unsigned int saddr = (unsigned int)__cvta_generic_to_shared(srcp);
            asm volatile(
                "cp.async.bulk.global.shared::cta.bulk_group [%0], [%1], %2;"
                :: "l"(out + base + head), "r"(saddr), "r"(nf4 * 16)
                : "memory");
        }
    }
    if (lane == 0) {
        asm volatile("cp.async.bulk.commit_group;" ::: "memory");
        asm volatile("cp.async.bulk.wait_group 0;" ::: "memory");
    }
}

// ---------------- launch -----------------------------------------------------
extern "C" void kernel_launch(void* const* d_in, const int* in_sizes, int n_in,
                              void* d_out, int out_size) {
    const int*   inp    = (const int*)d_in[0];
    const float* hidden = (const float*)d_in[1];
    const float* emb    = (const float*)d_in[2];
    const float* bw     = (const float*)d_in[3];
    const float* bb     = (const float*)d_in[4];
    const float* w_ih   = (const float*)d_in[5];
    const float* w_hh   = (const float*)d_in[6];
    const float* b_ih   = (const float*)d_in[7];
    const float* b_hh   = (const float*)d_in[8];
    const float* pw     = (const float*)d_in[9];
    const float* pb     = (const float*)d_in[10];
    float* out = (float*)d_out;

    static int attr_done = 0;
    if (!attr_done) {
        cudaFuncSetAttribute(k2_proj,
            cudaFuncAttributeMaxDynamicSharedMemorySize, K2_SMEM);
        attr_done = 1;
    }

    k0_prep<<<64, 256>>>(inp, hidden, emb, bw, bb);
    k1a_gemm<<<96, 128>>>(w_ih, w_hh, b_ih, b_hh);
    k1b_nonlin<<<64, 256>>>();
    k2_proj<<<NB2, 128, K2_SMEM>>>(pw, pb); // <-- ncu slot 6 (4th launch)
    k4_bcast<<<16 * 16 * 4, 256>>>(out);
}